// round 1
// baseline (speedup 1.0000x reference)
#include <cuda_runtime.h>
#include <cuda_bf16.h>

// ---------------- problem constants ----------------
#define N_NODES  50000
#define N_EDGES  800000
#define IN_F     128
#define HEADS    8
#define OUT_F    32
#define HD       256          // HEADS*OUT_F
#define NEXT     272          // HD + 8 (el) + 8 (er)
#define NEXT_PAD 320          // padded to 5*64 for GEMM tiling
#define NEG_SLOPE 0.2f

// ---------------- device scratch (static, allocation-free) ----------------
__device__ float g_feat_hd[N_NODES * HD];     // 51.2 MB
__device__ float g_el[N_NODES * HEADS];
__device__ float g_er[N_NODES * HEADS];
__device__ float g_w[N_EDGES * HEADS];        // 25.6 MB unnormalized softmax weights
__device__ float g_wext[NEXT_PAD * IN_F];     // W rows + al2 + ar2 + zero pad
__device__ int   g_count[N_NODES];
__device__ int   g_off[N_NODES + 1];
__device__ int   g_cursor[N_NODES];
__device__ int2  g_epair[N_EDGES];            // (src, original edge id) sorted by dst

// ---------------- CSR build ----------------
__global__ void zero_counts_kernel() {
    int i = blockIdx.x * blockDim.x + threadIdx.x;
    if (i < N_NODES) g_count[i] = 0;
}

__global__ void hist_kernel(const int* __restrict__ dst) {
    int e = blockIdx.x * blockDim.x + threadIdx.x;
    if (e < N_EDGES) atomicAdd(&g_count[dst[e]], 1);
}

__global__ void scan_kernel() {
    __shared__ int sh[1024];
    int tid = threadIdx.x;
    const int chunk = (N_NODES + 1023) / 1024;  // 49
    int begin = tid * chunk;
    int end   = begin + chunk; if (end > N_NODES) end = N_NODES;
    if (begin > N_NODES) begin = N_NODES;
    int s = 0;
    for (int i = begin; i < end; i++) s += g_count[i];
    sh[tid] = s;
    __syncthreads();
    // Hillis-Steele inclusive scan
    for (int off = 1; off < 1024; off <<= 1) {
        int v = (tid >= off) ? sh[tid - off] : 0;
        __syncthreads();
        sh[tid] += v;
        __syncthreads();
    }
    int prefix = (tid == 0) ? 0 : sh[tid - 1];
    for (int i = begin; i < end; i++) {
        g_off[i]    = prefix;
        g_cursor[i] = prefix;
        prefix += g_count[i];
    }
    if (tid == 1023) g_off[N_NODES] = sh[1023];
}

__global__ void scatter_kernel(const int* __restrict__ src, const int* __restrict__ dst) {
    int e = blockIdx.x * blockDim.x + threadIdx.x;
    if (e >= N_EDGES) return;
    int d   = dst[e];
    int pos = atomicAdd(&g_cursor[d], 1);
    g_epair[pos] = make_int2(src[e], e);
}

// ---------------- build extended weight matrix ----------------
// rows [0,256): W_fc;  rows [256,264): al2[h,:]=sum_d attn_l[h,d]*W[h*32+d,:]
// rows [264,272): ar2;  rows [272,320): zero padding
__global__ void build_wext_kernel(const float* __restrict__ W,
                                  const float* __restrict__ al,
                                  const float* __restrict__ ar) {
    int idx = blockIdx.x * blockDim.x + threadIdx.x;
    if (idx >= NEXT_PAD * IN_F) return;
    int j = idx / IN_F;
    int k = idx % IN_F;
    float v = 0.0f;
    if (j < HD) {
        v = W[j * IN_F + k];
    } else if (j < HD + HEADS) {
        int h = j - HD;
        float s = 0.0f;
        for (int d = 0; d < OUT_F; d++)
            s += al[h * OUT_F + d] * W[(h * OUT_F + d) * IN_F + k];
        v = s;
    } else if (j < HD + 2 * HEADS) {
        int h = j - HD - HEADS;
        float s = 0.0f;
        for (int d = 0; d < OUT_F; d++)
            s += ar[h * OUT_F + d] * W[(h * OUT_F + d) * IN_F + k];
        v = s;
    }
    g_wext[idx] = v;
}

// ---------------- GEMM: C[M, 272] = feat[M,128] @ wext^T ----------------
#define BM 64
#define BN 64
#define BK 16
__global__ void gemm_kernel(const float* __restrict__ A) {
    __shared__ float As[BK][BM + 4];
    __shared__ float Bs[BK][BN + 4];
    const int bm  = blockIdx.x * BM;
    const int bn  = blockIdx.y * BN;
    const int tid = threadIdx.x;          // 256 threads
    const int tx  = tid % 16;
    const int ty  = tid / 16;
    const int lr  = tid / 4;              // 0..63
    const int lk4 = (tid % 4) * 4;        // 0,4,8,12

    float acc[4][4] = {};

    for (int k0 = 0; k0 < IN_F; k0 += BK) {
        int arow = bm + lr;
        float4 av;
        if (arow < N_NODES)
            av = *reinterpret_cast<const float4*>(A + (size_t)arow * IN_F + k0 + lk4);
        else
            av = make_float4(0.f, 0.f, 0.f, 0.f);
        As[lk4 + 0][lr] = av.x; As[lk4 + 1][lr] = av.y;
        As[lk4 + 2][lr] = av.z; As[lk4 + 3][lr] = av.w;

        float4 bv = *reinterpret_cast<const float4*>(g_wext + (size_t)(bn + lr) * IN_F + k0 + lk4);
        Bs[lk4 + 0][lr] = bv.x; Bs[lk4 + 1][lr] = bv.y;
        Bs[lk4 + 2][lr] = bv.z; Bs[lk4 + 3][lr] = bv.w;

        __syncthreads();
        #pragma unroll
        for (int k = 0; k < BK; k++) {
            float a[4], b[4];
            #pragma unroll
            for (int i = 0; i < 4; i++) a[i] = As[k][ty * 4 + i];
            #pragma unroll
            for (int j = 0; j < 4; j++) b[j] = Bs[k][tx * 4 + j];
            #pragma unroll
            for (int i = 0; i < 4; i++)
                #pragma unroll
                for (int j = 0; j < 4; j++)
                    acc[i][j] = fmaf(a[i], b[j], acc[i][j]);
        }
        __syncthreads();
    }

    #pragma unroll
    for (int i = 0; i < 4; i++) {
        int row = bm + ty * 4 + i;
        if (row >= N_NODES) continue;
        #pragma unroll
        for (int j = 0; j < 4; j++) {
            int col = bn + tx * 4 + j;
            float v = acc[i][j];
            if (col < HD)                  g_feat_hd[(size_t)row * HD + col] = v;
            else if (col < HD + HEADS)     g_el[row * HEADS + (col - HD)] = v;
            else if (col < HD + 2 * HEADS) g_er[row * HEADS + (col - HD - HEADS)] = v;
        }
    }
}

// ---------------- per-edge unnormalized softmax weights ----------------
// No max-subtraction needed: |logit| <~ 6, exp stays comfortably in f32 range,
// and softmax is shift-invariant so the normalized result matches the reference.
__global__ void weight_kernel(const int* __restrict__ src, const int* __restrict__ dst) {
    int e = blockIdx.x * blockDim.x + threadIdx.x;
    if (e >= N_EDGES) return;
    int s = src[e];
    int d = dst[e];
    const float4* elp = reinterpret_cast<const float4*>(g_el + s * HEADS);
    const float4* erp = reinterpret_cast<const float4*>(g_er + d * HEADS);
    float4 a0 = elp[0], a1 = elp[1];
    float4 b0 = erp[0], b1 = erp[1];
    float t[8];
    t[0] = a0.x + b0.x; t[1] = a0.y + b0.y; t[2] = a0.z + b0.z; t[3] = a0.w + b0.w;
    t[4] = a1.x + b1.x; t[5] = a1.y + b1.y; t[6] = a1.z + b1.z; t[7] = a1.w + b1.w;
    float w[8];
    #pragma unroll
    for (int h = 0; h < 8; h++) {
        float x = t[h];
        x = (x > 0.0f) ? x : NEG_SLOPE * x;
        w[h] = __expf(x);
    }
    float4* wp = reinterpret_cast<float4*>(g_w + (size_t)e * HEADS);
    wp[0] = make_float4(w[0], w[1], w[2], w[3]);
    wp[1] = make_float4(w[4], w[5], w[6], w[7]);
}

// ---------------- aggregation: warp per dst node over CSR ----------------
// lane owns float4 chunks q1=lane and q2=lane+32 of the 64-float4 (256-float) row.
// chunk q covers head h = q/8. Coalesced 128B loads of feat_hd rows; no atomics.
__global__ void agg_kernel(float* __restrict__ out) {
    int warp = (blockIdx.x * blockDim.x + threadIdx.x) >> 5;
    int lane = threadIdx.x & 31;
    if (warp >= N_NODES) return;
    int n  = warp;
    int p0 = g_off[n];
    int p1 = g_off[n + 1];

    int h1 = lane >> 3;          // head for chunk q1 (0..3)
    // head for chunk q2 is h1+4
    float4 acc1 = make_float4(0.f, 0.f, 0.f, 0.f);
    float4 acc2 = make_float4(0.f, 0.f, 0.f, 0.f);
    float z1 = 0.f, z2 = 0.f;

    for (int p = p0; p < p1; p++) {
        int2 pe = g_epair[p];                   // .x = src node, .y = edge id
        float w1 = g_w[(size_t)pe.y * HEADS + h1];
        float w2 = g_w[(size_t)pe.y * HEADS + h1 + 4];
        const float4* row = reinterpret_cast<const float4*>(g_feat_hd + (size_t)pe.x * HD);
        float4 f1 = row[lane];
        float4 f2 = row[lane + 32];
        acc1.x = fmaf(w1, f1.x, acc1.x); acc1.y = fmaf(w1, f1.y, acc1.y);
        acc1.z = fmaf(w1, f1.z, acc1.z); acc1.w = fmaf(w1, f1.w, acc1.w);
        acc2.x = fmaf(w2, f2.x, acc2.x); acc2.y = fmaf(w2, f2.y, acc2.y);
        acc2.z = fmaf(w2, f2.z, acc2.z); acc2.w = fmaf(w2, f2.w, acc2.w);
        z1 += w1; z2 += w2;
    }

    float4 o1, o2;
    if (p1 > p0) {
        float i1 = 1.0f / z1;
        float i2 = 1.0f / z2;
        o1 = make_float4(acc1.x * i1, acc1.y * i1, acc1.z * i1, acc1.w * i1);
        o2 = make_float4(acc2.x * i2, acc2.y * i2, acc2.z * i2, acc2.w * i2);
    } else {
        o1 = make_float4(0.f, 0.f, 0.f, 0.f);
        o2 = o1;
    }
    float4* orow = reinterpret_cast<float4*>(out + (size_t)n * HD);
    orow[lane]      = o1;
    orow[lane + 32] = o2;
}

// ---------------- launch ----------------
extern "C" void kernel_launch(void* const* d_in, const int* in_sizes, int n_in,
                              void* d_out, int out_size) {
    const float* feat = (const float*)d_in[0];
    const float* W_fc = (const float*)d_in[1];
    const float* al   = (const float*)d_in[2];
    const float* ar   = (const float*)d_in[3];
    const int*   src  = (const int*)d_in[4];
    const int*   dst  = (const int*)d_in[5];
    float* out = (float*)d_out;

    // CSR build by dst
    zero_counts_kernel<<<(N_NODES + 255) / 256, 256>>>();
    hist_kernel<<<(N_EDGES + 255) / 256, 256>>>(dst);
    scan_kernel<<<1, 1024>>>();
    scatter_kernel<<<(N_EDGES + 255) / 256, 256>>>(src, dst);

    // projection + fused logit GEMM
    build_wext_kernel<<<(NEXT_PAD * IN_F + 255) / 256, 256>>>(W_fc, al, ar);
    dim3 ggrid((N_NODES + BM - 1) / BM, NEXT_PAD / BN);
    gemm_kernel<<<ggrid, 256>>>(feat);

    // edge weights + aggregation
    weight_kernel<<<(N_EDGES + 255) / 256, 256>>>(src, dst);
    agg_kernel<<<(N_NODES * 32 + 255) / 256, 256>>>(out);
}

// round 2
// speedup vs baseline: 1.3067x; 1.3067x over previous
#include <cuda_runtime.h>
#include <cuda_bf16.h>
#include <cstdint>

// ---------------- problem constants ----------------
#define N_NODES  50000
#define N_EDGES  800000
#define IN_F     128
#define HEADS    8
#define OUT_F    32
#define HD       256          // HEADS*OUT_F
#define NEXT_PAD 320          // 5 * 64 for GEMM tiling (272 real + pad)
#define NEG_SLOPE 0.2f

// ---------------- device scratch (static, allocation-free) ----------------
__device__ float g_feat_hd[N_NODES * HD];     // 51.2 MB
__device__ float g_el[N_NODES * HEADS];
__device__ float g_er[N_NODES * HEADS];
__device__ float g_w[N_EDGES * HEADS];        // 25.6 MB unnormalized softmax weights
__device__ float g_wext[NEXT_PAD * IN_F];     // W rows + al2 + ar2 + zero pad
__device__ int   g_count[N_NODES];
__device__ int   g_off[N_NODES + 1];
__device__ int   g_cursor[N_NODES];
__device__ int2  g_epair[N_EDGES];            // (src, original edge id) grouped by dst

// ---------------- CSR build ----------------
__global__ void zero_counts_kernel() {
    int i = blockIdx.x * blockDim.x + threadIdx.x;
    if (i < N_NODES) g_count[i] = 0;
}

__global__ void hist_kernel(const int* __restrict__ dst) {
    int e = blockIdx.x * blockDim.x + threadIdx.x;
    if (e < N_EDGES) atomicAdd(&g_count[dst[e]], 1);
}

__global__ void scan_kernel() {
    __shared__ int sh[1024];
    int tid = threadIdx.x;
    const int chunk = (N_NODES + 1023) / 1024;  // 49
    int begin = tid * chunk;
    int end   = begin + chunk; if (end > N_NODES) end = N_NODES;
    if (begin > N_NODES) begin = N_NODES;
    int s = 0;
    for (int i = begin; i < end; i++) s += g_count[i];
    sh[tid] = s;
    __syncthreads();
    for (int off = 1; off < 1024; off <<= 1) {
        int v = (tid >= off) ? sh[tid - off] : 0;
        __syncthreads();
        sh[tid] += v;
        __syncthreads();
    }
    int prefix = (tid == 0) ? 0 : sh[tid - 1];
    for (int i = begin; i < end; i++) {
        g_off[i]    = prefix;
        g_cursor[i] = prefix;
        prefix += g_count[i];
    }
    if (tid == 1023) g_off[N_NODES] = sh[1023];
}

__global__ void scatter_kernel(const int* __restrict__ src, const int* __restrict__ dst) {
    int e = blockIdx.x * blockDim.x + threadIdx.x;
    if (e >= N_EDGES) return;
    int d   = dst[e];
    int pos = atomicAdd(&g_cursor[d], 1);
    g_epair[pos] = make_int2(src[e], e);
}

// ---------------- build extended weight matrix ----------------
// rows [0,256): W_fc;  rows [256,264): al2[h,:]=sum_d attn_l[h,d]*W[h*32+d,:]
// rows [264,272): ar2;  rows [272,320): zero padding
__global__ void build_wext_kernel(const float* __restrict__ W,
                                  const float* __restrict__ al,
                                  const float* __restrict__ ar) {
    int idx = blockIdx.x * blockDim.x + threadIdx.x;
    if (idx >= NEXT_PAD * IN_F) return;
    int j = idx / IN_F;
    int k = idx % IN_F;
    float v = 0.0f;
    if (j < HD) {
        v = W[j * IN_F + k];
    } else if (j < HD + HEADS) {
        int h = j - HD;
        float s = 0.0f;
        for (int d = 0; d < OUT_F; d++)
            s += al[h * OUT_F + d] * W[(h * OUT_F + d) * IN_F + k];
        v = s;
    } else if (j < HD + 2 * HEADS) {
        int h = j - HD - HEADS;
        float s = 0.0f;
        for (int d = 0; d < OUT_F; d++)
            s += ar[h * OUT_F + d] * W[(h * OUT_F + d) * IN_F + k];
        v = s;
    }
    g_wext[idx] = v;
}

// ---------------- tf32 tensor-core GEMM ----------------
// C[M, 320] = feat[M,128] @ wext^T, via mma.sync.m16n8k8.tf32
// Block: 128x64 tile, full K=128 staged once in smem. 8 warps, 32x32 warp tiles.
// smem stride 132 floats -> fragment LDS bank = (4m + k) mod 32, conflict-free.
#define GSTR 132

__device__ __forceinline__ float cvt_tf32(float x) {
    float y;
    asm("cvt.rna.tf32.f32 %0, %1;" : "=f"(y) : "f"(x));
    return y;
}

__global__ void __launch_bounds__(256, 2) gemm_tf32_kernel(const float* __restrict__ A) {
    extern __shared__ float sh[];
    float* As = sh;                  // [128][GSTR]
    float* Bs = sh + 128 * GSTR;     // [64][GSTR]
    const int bm  = blockIdx.x * 128;
    const int bn  = blockIdx.y * 64;
    const int tid = threadIdx.x;     // 256 threads

    // ---- stage A tile (128 x 128), converted to tf32, STS.128 ----
    #pragma unroll
    for (int i = 0; i < 16; i++) {
        int pos = tid + i * 256;           // 0..4095
        int row = pos >> 5;
        int c4  = (pos & 31) << 2;
        float4 v = make_float4(0.f, 0.f, 0.f, 0.f);
        int gr = bm + row;
        if (gr < N_NODES)
            v = *reinterpret_cast<const float4*>(A + (size_t)gr * IN_F + c4);
        float4 t = make_float4(cvt_tf32(v.x), cvt_tf32(v.y), cvt_tf32(v.z), cvt_tf32(v.w));
        *reinterpret_cast<float4*>(As + row * GSTR + c4) = t;
    }
    // ---- stage B tile (64 x 128) ----
    #pragma unroll
    for (int i = 0; i < 8; i++) {
        int pos = tid + i * 256;           // 0..2047
        int row = pos >> 5;
        int c4  = (pos & 31) << 2;
        float4 v = *reinterpret_cast<const float4*>(g_wext + (size_t)(bn + row) * IN_F + c4);
        float4 t = make_float4(cvt_tf32(v.x), cvt_tf32(v.y), cvt_tf32(v.z), cvt_tf32(v.w));
        *reinterpret_cast<float4*>(Bs + row * GSTR + c4) = t;
    }
    __syncthreads();

    const int warp = tid >> 5;
    const int lane = tid & 31;
    const int wm = warp >> 1;        // 0..3
    const int wn = warp & 1;         // 0..1
    const int qr = lane >> 2;        // 0..7
    const int qc = lane & 3;         // 0..3

    float acc[2][4][4];
    #pragma unroll
    for (int mt = 0; mt < 2; mt++)
        #pragma unroll
        for (int nt = 0; nt < 4; nt++)
            #pragma unroll
            for (int r = 0; r < 4; r++) acc[mt][nt][r] = 0.f;

    #pragma unroll
    for (int ks = 0; ks < 16; ks++) {
        const int k0 = ks * 8;
        uint32_t a[2][4];
        #pragma unroll
        for (int mt = 0; mt < 2; mt++) {
            int m = wm * 32 + mt * 16 + qr;
            const float* p0 = As + m * GSTR + k0 + qc;
            const float* p1 = As + (m + 8) * GSTR + k0 + qc;
            a[mt][0] = __float_as_uint(p0[0]);
            a[mt][1] = __float_as_uint(p1[0]);
            a[mt][2] = __float_as_uint(p0[4]);
            a[mt][3] = __float_as_uint(p1[4]);
        }
        uint32_t b[4][2];
        #pragma unroll
        for (int nt = 0; nt < 4; nt++) {
            int n = wn * 32 + nt * 8 + qr;
            const float* p = Bs + n * GSTR + k0 + qc;
            b[nt][0] = __float_as_uint(p[0]);
            b[nt][1] = __float_as_uint(p[4]);
        }
        #pragma unroll
        for (int mt = 0; mt < 2; mt++)
            #pragma unroll
            for (int nt = 0; nt < 4; nt++) {
                asm volatile(
                    "mma.sync.aligned.m16n8k8.row.col.f32.tf32.tf32.f32 "
                    "{%0,%1,%2,%3}, {%4,%5,%6,%7}, {%8,%9}, {%0,%1,%2,%3};\n"
                    : "+f"(acc[mt][nt][0]), "+f"(acc[mt][nt][1]),
                      "+f"(acc[mt][nt][2]), "+f"(acc[mt][nt][3])
                    : "r"(a[mt][0]), "r"(a[mt][1]), "r"(a[mt][2]), "r"(a[mt][3]),
                      "r"(b[nt][0]), "r"(b[nt][1]));
            }
    }

    // ---- epilogue: scatter into feat_hd / el / er (float2 stores) ----
    #pragma unroll
    for (int mt = 0; mt < 2; mt++) {
        #pragma unroll
        for (int i = 0; i < 2; i++) {
            int row = bm + wm * 32 + mt * 16 + qr + i * 8;
            if (row >= N_NODES) continue;
            #pragma unroll
            for (int nt = 0; nt < 4; nt++) {
                int col = bn + wn * 32 + nt * 8 + 2 * qc;
                float2 v = make_float2(acc[mt][nt][2 * i], acc[mt][nt][2 * i + 1]);
                if (col < HD) {
                    *reinterpret_cast<float2*>(g_feat_hd + (size_t)row * HD + col) = v;
                } else if (col < HD + HEADS) {
                    *reinterpret_cast<float2*>(g_el + row * HEADS + (col - HD)) = v;
                } else if (col < HD + 2 * HEADS) {
                    *reinterpret_cast<float2*>(g_er + row * HEADS + (col - HD - HEADS)) = v;
                }
            }
        }
    }
}

// ---------------- per-edge unnormalized softmax weights ----------------
// Max-subtraction skipped: logits are small (|e| <~ 6), softmax shift-invariant.
__global__ void weight_kernel(const int* __restrict__ src, const int* __restrict__ dst) {
    int e = blockIdx.x * blockDim.x + threadIdx.x;
    if (e >= N_EDGES) return;
    int s = src[e];
    int d = dst[e];
    const float4* elp = reinterpret_cast<const float4*>(g_el + s * HEADS);
    const float4* erp = reinterpret_cast<const float4*>(g_er + d * HEADS);
    float4 a0 = elp[0], a1 = elp[1];
    float4 b0 = erp[0], b1 = erp[1];
    float t[8];
    t[0] = a0.x + b0.x; t[1] = a0.y + b0.y; t[2] = a0.z + b0.z; t[3] = a0.w + b0.w;
    t[4] = a1.x + b1.x; t[5] = a1.y + b1.y; t[6] = a1.z + b1.z; t[7] = a1.w + b1.w;
    float w[8];
    #pragma unroll
    for (int h = 0; h < 8; h++) {
        float x = t[h];
        x = (x > 0.0f) ? x : NEG_SLOPE * x;
        w[h] = __expf(x);
    }
    float4* wp = reinterpret_cast<float4*>(g_w + (size_t)e * HEADS);
    wp[0] = make_float4(w[0], w[1], w[2], w[3]);
    wp[1] = make_float4(w[4], w[5], w[6], w[7]);
}

// ---------------- aggregation: warp per dst node over CSR ----------------
__global__ void agg_kernel(float* __restrict__ out) {
    int warp = (blockIdx.x * blockDim.x + threadIdx.x) >> 5;
    int lane = threadIdx.x & 31;
    if (warp >= N_NODES) return;
    int n  = warp;
    int p0 = g_off[n];
    int p1 = g_off[n + 1];

    int h1 = lane >> 3;          // head for chunk q1 (0..3); q2 head = h1+4
    float4 acc1 = make_float4(0.f, 0.f, 0.f, 0.f);
    float4 acc2 = make_float4(0.f, 0.f, 0.f, 0.f);
    float z1 = 0.f, z2 = 0.f;

    for (int p = p0; p < p1; p++) {
        int2 pe = g_epair[p];                   // .x = src node, .y = edge id
        float w1 = g_w[(size_t)pe.y * HEADS + h1];
        float w2 = g_w[(size_t)pe.y * HEADS + h1 + 4];
        const float4* row = reinterpret_cast<const float4*>(g_feat_hd + (size_t)pe.x * HD);
        float4 f1 = row[lane];
        float4 f2 = row[lane + 32];
        acc1.x = fmaf(w1, f1.x, acc1.x); acc1.y = fmaf(w1, f1.y, acc1.y);
        acc1.z = fmaf(w1, f1.z, acc1.z); acc1.w = fmaf(w1, f1.w, acc1.w);
        acc2.x = fmaf(w2, f2.x, acc2.x); acc2.y = fmaf(w2, f2.y, acc2.y);
        acc2.z = fmaf(w2, f2.z, acc2.z); acc2.w = fmaf(w2, f2.w, acc2.w);
        z1 += w1; z2 += w2;
    }

    float4 o1, o2;
    if (p1 > p0) {
        float i1 = 1.0f / z1;
        float i2 = 1.0f / z2;
        o1 = make_float4(acc1.x * i1, acc1.y * i1, acc1.z * i1, acc1.w * i1);
        o2 = make_float4(acc2.x * i2, acc2.y * i2, acc2.z * i2, acc2.w * i2);
    } else {
        o1 = make_float4(0.f, 0.f, 0.f, 0.f);
        o2 = o1;
    }
    float4* orow = reinterpret_cast<float4*>(out + (size_t)n * HD);
    orow[lane]      = o1;
    orow[lane + 32] = o2;
}

// ---------------- launch ----------------
extern "C" void kernel_launch(void* const* d_in, const int* in_sizes, int n_in,
                              void* d_out, int out_size) {
    const float* feat = (const float*)d_in[0];
    const float* W_fc = (const float*)d_in[1];
    const float* al   = (const float*)d_in[2];
    const float* ar   = (const float*)d_in[3];
    const int*   src  = (const int*)d_in[4];
    const int*   dst  = (const int*)d_in[5];
    float* out = (float*)d_out;

    // CSR build by dst
    zero_counts_kernel<<<(N_NODES + 255) / 256, 256>>>();
    hist_kernel<<<(N_EDGES + 255) / 256, 256>>>(dst);
    scan_kernel<<<1, 1024>>>();
    scatter_kernel<<<(N_EDGES + 255) / 256, 256>>>(src, dst);

    // projection + fused logit GEMM (tf32 tensor cores)
    build_wext_kernel<<<(NEXT_PAD * IN_F + 255) / 256, 256>>>(W_fc, al, ar);
    const int smem_bytes = (128 * GSTR + 64 * GSTR) * sizeof(float);   // ~101 KB
    cudaFuncSetAttribute(gemm_tf32_kernel,
                         cudaFuncAttributeMaxDynamicSharedMemorySize, smem_bytes);
    dim3 ggrid((N_NODES + 127) / 128, NEXT_PAD / 64);
    gemm_tf32_kernel<<<ggrid, 256, smem_bytes>>>(feat);

    // edge weights + aggregation
    weight_kernel<<<(N_EDGES + 255) / 256, 256>>>(src, dst);
    agg_kernel<<<(N_NODES * 32 + 255) / 256, 256>>>(out);
}

// round 3
// speedup vs baseline: 2.8489x; 2.1802x over previous
#include <cuda_runtime.h>
#include <cuda_fp16.h>
#include <cstdint>

// ---------------- problem constants ----------------
#define N_NODES  50000
#define N_EDGES  800000
#define IN_F     128
#define HEADS    8
#define OUT_F    32
#define HD       256          // HEADS*OUT_F
#define NEXT_PAD 320          // 5 * 64 for GEMM tiling (272 real + pad)
#define NEG_SLOPE 0.2f

// ---------------- device scratch (static, allocation-free) ----------------
__device__ __align__(16) __half g_feat_h[N_NODES * HD];   // 25.6 MB fp16 messages
__device__ float g_el[N_NODES * HEADS];
__device__ float g_er[N_NODES * HEADS];
__device__ float g_wext[NEXT_PAD * IN_F];     // tf32-rounded W rows + al2 + ar2 + pad
__device__ int   g_count[N_NODES];
__device__ int   g_off[N_NODES];
__device__ int   g_cursor[N_NODES];
__device__ int   g_total;
__device__ int   g_esrc[N_EDGES];             // src node per edge, grouped by dst

// ---------------- CSR build ----------------
__global__ void zero_counts_kernel() {
    int i = blockIdx.x * blockDim.x + threadIdx.x;
    if (i < N_NODES) g_count[i] = 0;
    if (i == 0) g_total = 0;
}

__global__ void hist_kernel(const int* __restrict__ dst) {
    int e = blockIdx.x * blockDim.x + threadIdx.x;
    if (e < N_EDGES) atomicAdd(&g_count[dst[e]], 1);
}

// Segment offsets via warp scan + one atomic per warp. Segment placement is
// order-nondeterministic but per-node sums are unchanged.
__global__ void offsets_kernel() {
    int n    = blockIdx.x * blockDim.x + threadIdx.x;
    int lane = threadIdx.x & 31;
    int c = (n < N_NODES) ? g_count[n] : 0;
    int incl = c;
    #pragma unroll
    for (int d = 1; d < 32; d <<= 1) {
        int v = __shfl_up_sync(0xffffffffu, incl, d);
        if (lane >= d) incl += v;
    }
    int total = __shfl_sync(0xffffffffu, incl, 31);
    int base = 0;
    if (lane == 31) base = atomicAdd(&g_total, total);
    base = __shfl_sync(0xffffffffu, base, 31);
    if (n < N_NODES) {
        int off = base + incl - c;
        g_off[n]    = off;
        g_cursor[n] = off;
    }
}

__global__ void scatter_kernel(const int* __restrict__ src, const int* __restrict__ dst) {
    int e = blockIdx.x * blockDim.x + threadIdx.x;
    if (e >= N_EDGES) return;
    int d   = dst[e];
    int pos = atomicAdd(&g_cursor[d], 1);
    g_esrc[pos] = src[e];
}

// ---------------- build extended weight matrix (tf32-rounded) ----------------
__device__ __forceinline__ float cvt_tf32(float x) {
    float y;
    asm("cvt.rna.tf32.f32 %0, %1;" : "=f"(y) : "f"(x));
    return y;
}

__global__ void build_wext_kernel(const float* __restrict__ W,
                                  const float* __restrict__ al,
                                  const float* __restrict__ ar) {
    int idx = blockIdx.x * blockDim.x + threadIdx.x;
    if (idx >= NEXT_PAD * IN_F) return;
    int j = idx / IN_F;
    int k = idx % IN_F;
    float v = 0.0f;
    if (j < HD) {
        v = W[j * IN_F + k];
    } else if (j < HD + HEADS) {
        int h = j - HD;
        float s = 0.0f;
        for (int d = 0; d < OUT_F; d++)
            s += al[h * OUT_F + d] * W[(h * OUT_F + d) * IN_F + k];
        v = s;
    } else if (j < HD + 2 * HEADS) {
        int h = j - HD - HEADS;
        float s = 0.0f;
        for (int d = 0; d < OUT_F; d++)
            s += ar[h * OUT_F + d] * W[(h * OUT_F + d) * IN_F + k];
        v = s;
    }
    g_wext[idx] = cvt_tf32(v);
}

// ---------------- tf32 tensor-core GEMM, cp.async double-buffered ----------------
// C[M, 320] = feat[M,128] @ wext^T, mma.sync.m16n8k8.tf32
// Block 128x64, BK=32, 2-stage cp.async pipeline. A truncated to tf32 by MMA HW,
// B pre-rounded (rna) in build_wext. smem stride 36 -> conflict-free fragment LDS.
#define BK   32
#define ASTR 36

__device__ __forceinline__ void cp_async16(uint32_t smem_addr, const void* gptr, int src_bytes) {
    asm volatile("cp.async.ca.shared.global [%0], [%1], 16, %2;\n"
                 :: "r"(smem_addr), "l"(gptr), "r"(src_bytes));
}

__global__ void __launch_bounds__(256, 3) gemm_tf32_kernel(const float* __restrict__ A) {
    extern __shared__ float sh[];
    // layout: As[2][128*ASTR], Bs[2][64*ASTR]
    float* Asb[2] = { sh,              sh + 128 * ASTR };
    float* Bsb[2] = { sh + 2 * 128 * ASTR, sh + 2 * 128 * ASTR + 64 * ASTR };
    const int bm  = blockIdx.x * 128;
    const int bn  = blockIdx.y * 64;
    const int tid = threadIdx.x;

    uint32_t sA[2], sB[2];
    sA[0] = (uint32_t)__cvta_generic_to_shared(Asb[0]);
    sA[1] = (uint32_t)__cvta_generic_to_shared(Asb[1]);
    sB[0] = (uint32_t)__cvta_generic_to_shared(Bsb[0]);
    sB[1] = (uint32_t)__cvta_generic_to_shared(Bsb[1]);

    const int srow = tid >> 3;           // staging row step: 32 rows / 256-thread pass
    const int skq  = (tid & 7) << 2;     // k quad

    auto stage = [&](int buf, int kc) {
        int k0 = kc * BK;
        #pragma unroll
        for (int it = 0; it < 4; it++) {
            int row = srow + it * 32;
            int gr  = bm + row;
            const float* src = A + (size_t)gr * IN_F + k0 + skq;
            cp_async16(sA[buf] + (row * ASTR + skq) * 4, src, gr < N_NODES ? 16 : 0);
        }
        #pragma unroll
        for (int it = 0; it < 2; it++) {
            int row = srow + it * 32;
            const float* src = g_wext + (size_t)(bn + row) * IN_F + k0 + skq;
            cp_async16(sB[buf] + (row * ASTR + skq) * 4, src, 16);
        }
        asm volatile("cp.async.commit_group;\n");
    };

    const int warp = tid >> 5;
    const int lane = tid & 31;
    const int wm = warp >> 1;        // 0..3
    const int wn = warp & 1;         // 0..1
    const int qr = lane >> 2;        // 0..7
    const int qc = lane & 3;         // 0..3

    float acc[2][4][4];
    #pragma unroll
    for (int mt = 0; mt < 2; mt++)
        #pragma unroll
        for (int nt = 0; nt < 4; nt++)
            #pragma unroll
            for (int r = 0; r < 4; r++) acc[mt][nt][r] = 0.f;

    stage(0, 0);

    #pragma unroll
    for (int kc = 0; kc < 4; kc++) {
        int buf = kc & 1;
        if (kc < 3) stage(buf ^ 1, kc + 1);
        if (kc < 3) asm volatile("cp.async.wait_group 1;\n");
        else        asm volatile("cp.async.wait_group 0;\n");
        __syncthreads();

        const float* cAs = Asb[buf];
        const float* cBs = Bsb[buf];
        #pragma unroll
        for (int ks = 0; ks < 4; ks++) {
            int k0 = ks * 8;
            uint32_t a[2][4];
            #pragma unroll
            for (int mt = 0; mt < 2; mt++) {
                const float* p = cAs + (wm * 32 + mt * 16 + qr) * ASTR + k0 + qc;
                a[mt][0] = __float_as_uint(p[0]);
                a[mt][1] = __float_as_uint(p[8 * ASTR]);
                a[mt][2] = __float_as_uint(p[4]);
                a[mt][3] = __float_as_uint(p[8 * ASTR + 4]);
            }
            uint32_t b[4][2];
            #pragma unroll
            for (int nt = 0; nt < 4; nt++) {
                const float* p = cBs + (wn * 32 + nt * 8 + qr) * ASTR + k0 + qc;
                b[nt][0] = __float_as_uint(p[0]);
                b[nt][1] = __float_as_uint(p[4]);
            }
            #pragma unroll
            for (int mt = 0; mt < 2; mt++)
                #pragma unroll
                for (int nt = 0; nt < 4; nt++) {
                    asm volatile(
                        "mma.sync.aligned.m16n8k8.row.col.f32.tf32.tf32.f32 "
                        "{%0,%1,%2,%3}, {%4,%5,%6,%7}, {%8,%9}, {%0,%1,%2,%3};\n"
                        : "+f"(acc[mt][nt][0]), "+f"(acc[mt][nt][1]),
                          "+f"(acc[mt][nt][2]), "+f"(acc[mt][nt][3])
                        : "r"(a[mt][0]), "r"(a[mt][1]), "r"(a[mt][2]), "r"(a[mt][3]),
                          "r"(b[nt][0]), "r"(b[nt][1]));
                }
        }
        __syncthreads();
    }

    // ---- epilogue: fp16 feat_hd + fp32 el/er ----
    #pragma unroll
    for (int mt = 0; mt < 2; mt++) {
        #pragma unroll
        for (int i = 0; i < 2; i++) {
            int row = bm + wm * 32 + mt * 16 + qr + i * 8;
            if (row >= N_NODES) continue;
            #pragma unroll
            for (int nt = 0; nt < 4; nt++) {
                int col = bn + wn * 32 + nt * 8 + 2 * qc;
                float v0 = acc[mt][nt][2 * i];
                float v1 = acc[mt][nt][2 * i + 1];
                if (col < HD) {
                    __half2 hv = __floats2half2_rn(v0, v1);
                    *reinterpret_cast<__half2*>(g_feat_h + (size_t)row * HD + col) = hv;
                } else if (col < HD + HEADS) {
                    *reinterpret_cast<float2*>(g_el + row * HEADS + (col - HD)) =
                        make_float2(v0, v1);
                } else if (col < HD + 2 * HEADS) {
                    *reinterpret_cast<float2*>(g_er + row * HEADS + (col - HD - HEADS)) =
                        make_float2(v0, v1);
                }
            }
        }
    }
}

// ---------------- fused softmax + aggregation: warp per dst node ----------------
// Lane owns 8 fp16 channels of head h = lane>>2 (one LDG.128 per edge per warp).
// w computed inline (softmax shift-invariance: no max pass; logits are small).
__global__ void agg_kernel(float* __restrict__ out) {
    int warp = (blockIdx.x * blockDim.x + threadIdx.x) >> 5;
    int lane = threadIdx.x & 31;
    if (warp >= N_NODES) return;
    int n   = warp;
    int p0  = g_off[n];
    int cnt = g_count[n];
    int h   = lane >> 2;
    float er_h = g_er[n * HEADS + h];

    float acc[8] = {};
    float z = 0.f;
    const uint4* fbase = reinterpret_cast<const uint4*>(g_feat_h);

    for (int p = p0; p < p0 + cnt; p++) {
        int s = g_esrc[p];
        float x = g_el[s * HEADS + h] + er_h;
        x = fmaxf(x, NEG_SLOPE * x);          // leaky relu
        float w = __expf(x);                   // unnormalized softmax weight
        uint4 q = fbase[(size_t)s * (HD / 8) + lane];
        const __half2* hh = reinterpret_cast<const __half2*>(&q);
        #pragma unroll
        for (int j = 0; j < 4; j++) {
            float2 f = __half22float2(hh[j]);
            acc[2 * j]     = fmaf(w, f.x, acc[2 * j]);
            acc[2 * j + 1] = fmaf(w, f.y, acc[2 * j + 1]);
        }
        z += w;
    }

    float inv = (cnt > 0) ? (1.0f / z) : 0.f;
    float* orow = out + (size_t)n * HD + lane * 8;
    *reinterpret_cast<float4*>(orow) =
        make_float4(acc[0] * inv, acc[1] * inv, acc[2] * inv, acc[3] * inv);
    *reinterpret_cast<float4*>(orow + 4) =
        make_float4(acc[4] * inv, acc[5] * inv, acc[6] * inv, acc[7] * inv);
}

// ---------------- launch ----------------
extern "C" void kernel_launch(void* const* d_in, const int* in_sizes, int n_in,
                              void* d_out, int out_size) {
    const float* feat = (const float*)d_in[0];
    const float* W_fc = (const float*)d_in[1];
    const float* al   = (const float*)d_in[2];
    const float* ar   = (const float*)d_in[3];
    const int*   src  = (const int*)d_in[4];
    const int*   dst  = (const int*)d_in[5];
    float* out = (float*)d_out;

    zero_counts_kernel<<<(N_NODES + 255) / 256, 256>>>();
    hist_kernel<<<(N_EDGES + 255) / 256, 256>>>(dst);
    offsets_kernel<<<(N_NODES + 255) / 256, 256>>>();
    scatter_kernel<<<(N_EDGES + 255) / 256, 256>>>(src, dst);

    build_wext_kernel<<<(NEXT_PAD * IN_F + 255) / 256, 256>>>(W_fc, al, ar);

    const int smem_bytes = 2 * (128 + 64) * ASTR * sizeof(float);   // 55296 B
    cudaFuncSetAttribute(gemm_tf32_kernel,
                         cudaFuncAttributeMaxDynamicSharedMemorySize, smem_bytes);
    dim3 ggrid((N_NODES + 127) / 128, NEXT_PAD / 64);
    gemm_tf32_kernel<<<ggrid, 256, smem_bytes>>>(feat);

    agg_kernel<<<(N_NODES * 32 + 255) / 256, 256>>>(out);
}